// round 16
// baseline (speedup 1.0000x reference)
#include <cuda_runtime.h>
#include <cuda_fp16.h>
#include <cstdint>

#define NI 50000
#define NO 5000
#define BATCH 128
#define NNZ_MAX 1000000
#define CAP 512    // bucket capacity per output col (mean 200, sigma ~14 -> 22 sigma)

// -------- scratch (static __device__ — zero-initialized at module load) --------
__device__ __half2 g_xTh[(size_t)NI * (BATCH / 2)]; // 12.8 MB, fp16 xT[i][b]
__device__ int2    g_edges[(size_t)NO * CAP];       // 20.5 MB, bucketed (row, w-bits)
__device__ int     g_cnt[NO];                       // zeroed by k_spmm epilogue each call

// decode 32 bits (two fp16) -> float2
__device__ __forceinline__ float2 h2f2(unsigned u) {
    __half2 h = *reinterpret_cast<__half2*>(&u);
    return __half22float2(h);
}

// packed fp32x2 helpers (Blackwell packed-fp32 pipe, sm_100+)
__device__ __forceinline__ unsigned long long pack2(float lo, float hi) {
    unsigned long long r;
    asm("mov.b64 %0, {%1, %2};" : "=l"(r) : "f"(lo), "f"(hi));
    return r;
}
__device__ __forceinline__ void unpack2(unsigned long long v, float& lo, float& hi) {
    asm("mov.b64 {%0, %1}, %2;" : "=f"(lo), "=f"(hi) : "l"(v));
}
__device__ __forceinline__ void ffma2(unsigned long long& acc,
                                      unsigned long long a, unsigned long long b) {
    asm("fma.rn.f32x2 %0, %1, %2, %0;" : "+l"(acc) : "l"(a), "l"(b));
}

// -------- 1: fused prep, block types INTERLEAVED (Bresenham over bid) --------
__global__ void __launch_bounds__(256) k_prep(const float* __restrict__ x,
                                              const void* __restrict__ conn,
                                              const float* __restrict__ w,
                                              int nnz, int s_blocks, int t_blocks) {
    int bid = blockIdx.x;
    int total = s_blocks + t_blocks;
    int tb  = (int)(((long long)bid * t_blocks) / total);
    int tb1 = (int)(((long long)(bid + 1) * t_blocks) / total);

    if (tb1 == tb) {
        // ---- bucket scatter block (index sid): one thread per edge ----
        int sid = bid - tb;
        int e = sid * 256 + threadIdx.x;
        bool valid = (e < nnz);
        int ce = valid ? e : 0;
        // int64 LE (values < 2^31): odd 32-bit word is zero high-half.
        // int32 (row,col) pairs: odd words are cols ~U[0,5000); all-zero prob ~5000^-32.
        int2 rc = ((const int2*)conn)[ce];
        unsigned m = __ballot_sync(0xffffffffu, valid && (rc.y != 0));
        bool is64 = (m == 0);
        if (!valid) return;

        int row, col;
        if (is64) {
            longlong2 c = ((const longlong2*)conn)[e];
            row = (int)c.x; col = (int)c.y;
        } else {
            row = rc.x; col = rc.y;
        }
        if ((unsigned)row < NI && (unsigned)col < NO) {
            int p = atomicAdd(&g_cnt[col], 1);
            if (p < CAP)
                g_edges[(size_t)col * CAP + p] = make_int2(row, __float_as_int(w[e]));
        }
    } else {
        // ---- transpose block (index tb): x (BATCH, NI) -> fp16 xT (NI, BATCH) ----
        // XOR-swizzled 16 KB tile: ZERO bank conflicts in both phases.
        __shared__ float tile[BATCH][32];
        int i0 = tb * 32;
        int tx = threadIdx.x & 31, ty = threadIdx.x >> 5;   // (32, 8)
        int i = i0 + tx;

        if (i < NI) {
            #pragma unroll
            for (int j = 0; j < 16; j++) {
                int b = ty + 8 * j;        // covers 0..127
                tile[b][tx ^ (b >> 2)] = x[(size_t)b * NI + i];
            }
        }
        __syncthreads();

        #pragma unroll
        for (int jj = 0; jj < 4; jj++) {
            int ii = ty + 8 * jj;          // 0..31 within stripe
            int gi = i0 + ii;
            if (gi < NI) {
                int c = ii ^ tx;           // swizzled column, same for all 4 rows
                __half2 h0 = __float22half2_rn(
                    make_float2(tile[4 * tx + 0][c], tile[4 * tx + 1][c]));
                __half2 h1 = __float22half2_rn(
                    make_float2(tile[4 * tx + 2][c], tile[4 * tx + 3][c]));
                float2 v;                  // pack as float2 for a single STG.64
                v.x = *reinterpret_cast<float*>(&h0);
                v.y = *reinterpret_cast<float*>(&h1);
                ((float2*)g_xTh)[(size_t)gi * 32 + tx] = v;
            }
        }
    }
}

// -------- 2: SpMM pull: 1 col/block, SoA edges in SMEM, f32x2 packed FMA --------
__global__ void __launch_bounds__(256) k_spmm(const float* __restrict__ bias,
                                              float* __restrict__ out) {
    __shared__ int    srow[CAP];           // 2 KB
    __shared__ float  swt[CAP];            // 2 KB
    __shared__ float4 red[7][32];          // 3.5 KB: partials from segs 1..7

    int seg  = threadIdx.x >> 5;           // 0..7 edge segment
    int lane = threadIdx.x & 31;
    int col  = blockIdx.x;                 // grid = NO

    int n = g_cnt[col];
    if (n > CAP) n = CAP;

    // cooperative stage: AoS global -> SoA smem
    const int2* __restrict__ gsrc = &g_edges[(size_t)col * CAP];
    for (int i = threadIdx.x; i < n; i += 256) {
        int2 q = gsrc[i];
        srow[i] = q.x;
        swt[i]  = __int_as_float(q.y);
    }
    __syncthreads();

    // segment bounds rounded to multiples of 8 (keeps LDS.128 alignment)
    int chunk = ((n + 63) >> 6) << 3;      // ceil(n/8) rounded up to mult of 8
    int e   = seg * chunk;
    int end = e + chunk;
    if (end > n) end = n;

    const float2* __restrict__ xTh = (const float2*)g_xTh;  // 4 halves per elem
    unsigned long long acc01 = pack2(0.f, 0.f);
    unsigned long long acc23 = pack2(0.f, 0.f);

    for (; e + 7 < end; e += 8) {          // x8 batch: MLP vs L2 latency
        int4   r0 = *(const int4*)(srow + e);       // LDS.128
        int4   r1 = *(const int4*)(srow + e + 4);
        float4 w0 = *(const float4*)(swt + e);      // LDS.128
        float4 w1 = *(const float4*)(swt + e + 4);
        float2 xv[8];
        xv[0] = xTh[(size_t)r0.x * 32 + lane];
        xv[1] = xTh[(size_t)r0.y * 32 + lane];
        xv[2] = xTh[(size_t)r0.z * 32 + lane];
        xv[3] = xTh[(size_t)r0.w * 32 + lane];
        xv[4] = xTh[(size_t)r1.x * 32 + lane];
        xv[5] = xTh[(size_t)r1.y * 32 + lane];
        xv[6] = xTh[(size_t)r1.z * 32 + lane];
        xv[7] = xTh[(size_t)r1.w * 32 + lane];
        float wv[8] = {w0.x, w0.y, w0.z, w0.w, w1.x, w1.y, w1.z, w1.w};
        #pragma unroll
        for (int j = 0; j < 8; j++) {
            float2 a = h2f2(__float_as_uint(xv[j].x));
            float2 b = h2f2(__float_as_uint(xv[j].y));
            unsigned long long wp = pack2(wv[j], wv[j]);
            ffma2(acc01, pack2(a.x, a.y), wp);
            ffma2(acc23, pack2(b.x, b.y), wp);
        }
    }
    for (; e < end; e++) {                 // tail < 8 edges
        float wv = swt[e];
        float2 xv = xTh[(size_t)srow[e] * 32 + lane];
        float2 a = h2f2(__float_as_uint(xv.x));
        float2 b = h2f2(__float_as_uint(xv.y));
        unsigned long long wp = pack2(wv, wv);
        ffma2(acc01, pack2(a.x, a.y), wp);
        ffma2(acc23, pack2(b.x, b.y), wp);
    }

    float4 acc;
    unpack2(acc01, acc.x, acc.y);
    unpack2(acc23, acc.z, acc.w);

    if (seg != 0) red[seg - 1][lane] = acc;
    __syncthreads();

    if (seg == 0) {
        float bv = __ldg(&bias[col]);
        acc.x += bv; acc.y += bv; acc.z += bv; acc.w += bv;
        #pragma unroll
        for (int s = 0; s < 7; s++) {
            float4 a = red[s][lane];
            acc.x += a.x; acc.y += a.y; acc.z += a.z; acc.w += a.w;
        }
        int b = lane * 4;
        out[(size_t)(b + 0) * NO + col] = acc.x;
        out[(size_t)(b + 1) * NO + col] = acc.y;
        out[(size_t)(b + 2) * NO + col] = acc.z;
        out[(size_t)(b + 3) * NO + col] = acc.w;
    }

    // restore zero-invariant for next call (single owner block per col;
    // all reads of g_cnt[col] happened before the barrier above)
    if (threadIdx.x == 0) g_cnt[col] = 0;
}

extern "C" void kernel_launch(void* const* d_in, const int* in_sizes, int n_in,
                              void* d_out, int out_size) {
    const float* x    = (const float*)d_in[0];
    const void*  conn = (const void*)d_in[1];
    const float* w    = (const float*)d_in[2];
    const float* bias = (const float*)d_in[3];
    float* out = (float*)d_out;
    int nnz = in_sizes[2];
    if (nnz > NNZ_MAX) nnz = NNZ_MAX;

    int s_blocks = (nnz + 255) / 256;
    int t_blocks = (NI + 31) / 32;

    k_prep<<<s_blocks + t_blocks, 256>>>(x, conn, w, nnz, s_blocks, t_blocks);
    k_spmm<<<NO, 256>>>(bias, out);
}

// round 17
// speedup vs baseline: 1.0573x; 1.0573x over previous
#include <cuda_runtime.h>
#include <cuda_fp16.h>
#include <cstdint>

#define NI 50000
#define NO 5000
#define BATCH 128
#define NNZ_MAX 1000000
#define CAP 512    // bucket capacity per output col (mean 200, sigma ~14 -> 22 sigma)

// -------- scratch (static __device__ — zero-initialized at module load) --------
__device__ __half2 g_xTh[(size_t)NI * (BATCH / 2)]; // 12.8 MB, fp16 xT[i][b]
__device__ int2    g_edges[(size_t)NO * CAP];       // 20.5 MB, bucketed (row, w-bits)
__device__ int     g_cnt[NO];                       // zeroed by k_spmm epilogue each call

// decode 32 bits (two fp16) -> float2
__device__ __forceinline__ float2 h2f2(unsigned u) {
    __half2 h = *reinterpret_cast<__half2*>(&u);
    return __half22float2(h);
}

// -------- 1: fused prep, block types INTERLEAVED (Bresenham over bid) --------
__global__ void __launch_bounds__(256) k_prep(const float* __restrict__ x,
                                              const void* __restrict__ conn,
                                              const float* __restrict__ w,
                                              int nnz, int s_blocks, int t_blocks) {
    int bid = blockIdx.x;
    int total = s_blocks + t_blocks;
    int tb  = (int)(((long long)bid * t_blocks) / total);
    int tb1 = (int)(((long long)(bid + 1) * t_blocks) / total);

    if (tb1 == tb) {
        // ---- bucket scatter block (index sid): one thread per edge ----
        int sid = bid - tb;
        int e = sid * 256 + threadIdx.x;
        bool valid = (e < nnz);
        int ce = valid ? e : 0;
        // int64 LE (values < 2^31): odd 32-bit word is zero high-half.
        // int32 (row,col) pairs: odd words are cols ~U[0,5000); all-zero prob ~5000^-32.
        int2 rc = ((const int2*)conn)[ce];
        unsigned m = __ballot_sync(0xffffffffu, valid && (rc.y != 0));
        bool is64 = (m == 0);
        if (!valid) return;

        int row, col;
        if (is64) {
            longlong2 c = ((const longlong2*)conn)[e];
            row = (int)c.x; col = (int)c.y;
        } else {
            row = rc.x; col = rc.y;
        }
        if ((unsigned)row < NI && (unsigned)col < NO) {
            int p = atomicAdd(&g_cnt[col], 1);
            if (p < CAP)
                g_edges[(size_t)col * CAP + p] = make_int2(row, __float_as_int(w[e]));
        }
    } else {
        // ---- transpose block (index tb): x (BATCH, NI) -> fp16 xT (NI, BATCH) ----
        // XOR-swizzled 16 KB tile: ZERO bank conflicts in both phases.
        __shared__ float tile[BATCH][32];
        int i0 = tb * 32;
        int tx = threadIdx.x & 31, ty = threadIdx.x >> 5;   // (32, 8)
        int i = i0 + tx;

        if (i < NI) {
            #pragma unroll
            for (int j = 0; j < 16; j++) {
                int b = ty + 8 * j;        // covers 0..127
                tile[b][tx ^ (b >> 2)] = x[(size_t)b * NI + i];
            }
        }
        __syncthreads();

        #pragma unroll
        for (int jj = 0; jj < 4; jj++) {
            int ii = ty + 8 * jj;          // 0..31 within stripe
            int gi = i0 + ii;
            if (gi < NI) {
                int c = ii ^ tx;           // swizzled column, same for all 4 rows
                __half2 h0 = __float22half2_rn(
                    make_float2(tile[4 * tx + 0][c], tile[4 * tx + 1][c]));
                __half2 h1 = __float22half2_rn(
                    make_float2(tile[4 * tx + 2][c], tile[4 * tx + 3][c]));
                float2 v;                  // pack as float2 for a single STG.64
                v.x = *reinterpret_cast<float*>(&h0);
                v.y = *reinterpret_cast<float*>(&h1);
                ((float2*)g_xTh)[(size_t)gi * 32 + tx] = v;
            }
        }
    }
}

// -------- 2: SpMM pull: 1 col/block, SoA edges in SMEM, 8 warps over eighths --------
// (exact R15 structure: measured 31.2us, occ 84.6%, issue 62.2%)
__global__ void __launch_bounds__(256) k_spmm(const float* __restrict__ bias,
                                              float* __restrict__ out) {
    __shared__ int    srow[CAP];           // 2 KB
    __shared__ float  swt[CAP];            // 2 KB
    __shared__ float4 red[7][32];          // 3.5 KB: partials from segs 1..7

    int seg  = threadIdx.x >> 5;           // 0..7 edge segment
    int lane = threadIdx.x & 31;
    int col  = blockIdx.x;                 // grid = NO

    int n = g_cnt[col];
    if (n > CAP) n = CAP;

    // cooperative stage: AoS global -> SoA smem
    const int2* __restrict__ gsrc = &g_edges[(size_t)col * CAP];
    for (int i = threadIdx.x; i < n; i += 256) {
        int2 q = gsrc[i];
        srow[i] = q.x;
        swt[i]  = __int_as_float(q.y);
    }
    __syncthreads();

    // segment bounds rounded to multiples of 8 (keeps LDS.128 alignment)
    int chunk = ((n + 63) >> 6) << 3;      // ceil(n/8) rounded up to mult of 8
    int e   = seg * chunk;
    int end = e + chunk;
    if (end > n) end = n;

    const float2* __restrict__ xTh = (const float2*)g_xTh;  // 4 halves per elem
    float4 acc = make_float4(0.f, 0.f, 0.f, 0.f);

    for (; e + 7 < end; e += 8) {          // x8 batch: MLP vs L2 latency
        int4   r0 = *(const int4*)(srow + e);       // LDS.128
        int4   r1 = *(const int4*)(srow + e + 4);
        float4 w0 = *(const float4*)(swt + e);      // LDS.128
        float4 w1 = *(const float4*)(swt + e + 4);
        float2 xv[8];
        xv[0] = xTh[(size_t)r0.x * 32 + lane];
        xv[1] = xTh[(size_t)r0.y * 32 + lane];
        xv[2] = xTh[(size_t)r0.z * 32 + lane];
        xv[3] = xTh[(size_t)r0.w * 32 + lane];
        xv[4] = xTh[(size_t)r1.x * 32 + lane];
        xv[5] = xTh[(size_t)r1.y * 32 + lane];
        xv[6] = xTh[(size_t)r1.z * 32 + lane];
        xv[7] = xTh[(size_t)r1.w * 32 + lane];
        float wv[8] = {w0.x, w0.y, w0.z, w0.w, w1.x, w1.y, w1.z, w1.w};
        #pragma unroll
        for (int j = 0; j < 8; j++) {
            float2 a = h2f2(__float_as_uint(xv[j].x));
            float2 b = h2f2(__float_as_uint(xv[j].y));
            acc.x += a.x * wv[j]; acc.y += a.y * wv[j];
            acc.z += b.x * wv[j]; acc.w += b.y * wv[j];
        }
    }
    for (; e < end; e++) {                 // tail < 8 edges
        float wv = swt[e];
        float2 xv = xTh[(size_t)srow[e] * 32 + lane];
        float2 a = h2f2(__float_as_uint(xv.x));
        float2 b = h2f2(__float_as_uint(xv.y));
        acc.x += a.x * wv; acc.y += a.y * wv;
        acc.z += b.x * wv; acc.w += b.y * wv;
    }

    if (seg != 0) red[seg - 1][lane] = acc;
    __syncthreads();

    if (seg == 0) {
        float bv = __ldg(&bias[col]);
        acc.x += bv; acc.y += bv; acc.z += bv; acc.w += bv;
        #pragma unroll
        for (int s = 0; s < 7; s++) {
            float4 a = red[s][lane];
            acc.x += a.x; acc.y += a.y; acc.z += a.z; acc.w += a.w;
        }
        int b = lane * 4;
        out[(size_t)(b + 0) * NO + col] = acc.x;
        out[(size_t)(b + 1) * NO + col] = acc.y;
        out[(size_t)(b + 2) * NO + col] = acc.z;
        out[(size_t)(b + 3) * NO + col] = acc.w;
    }

    // restore zero-invariant for next call (single owner block per col;
    // all reads of g_cnt[col] happened before the barrier above)
    if (threadIdx.x == 0) g_cnt[col] = 0;
}

extern "C" void kernel_launch(void* const* d_in, const int* in_sizes, int n_in,
                              void* d_out, int out_size) {
    const float* x    = (const float*)d_in[0];
    const void*  conn = (const void*)d_in[1];
    const float* w    = (const float*)d_in[2];
    const float* bias = (const float*)d_in[3];
    float* out = (float*)d_out;
    int nnz = in_sizes[2];
    if (nnz > NNZ_MAX) nnz = NNZ_MAX;

    int s_blocks = (nnz + 255) / 256;
    int t_blocks = (NI + 31) / 32;

    k_prep<<<s_blocks + t_blocks, 256>>>(x, conn, w, nnz, s_blocks, t_blocks);
    k_spmm<<<NO, 256>>>(bias, out);
}